// round 4
// baseline (speedup 1.0000x reference)
#include <cuda_runtime.h>
#include <cstdint>

// ConvEnhanced: 2x2 valid conv + ReLU -> channel 0.
// Quantum circuit collapses analytically: RZ layers are diagonal phases,
// CNOT layers are permutations; Z0 after two CNOT layers = Z0*Z1*Z3 on the
// RX product state => qval = cos(p00)*cos(p01)*cos(p11). qparams unused.
// Channel 1 = qval replicated over each 2x2 patch.
//
// x: [64,1,257,257] f32; out: [64,2,256,256] f32.
//
// R4: input fetched via cp.async.bulk (contiguous 9-row strips) -> no LDG
// front-batching -> no cross-CTA L1tex queue spread. One block = 2 tiles
// (both bulk copies issued up front), grid 1024 ~= one wave.
// Image bases are only 4B aligned (257*257*4), so bulk src is aligned down
// to 16B and smem is indexed with a per-image shift.

#define IN_HW   257
#define OUT_HW  256
#define IMG_E   (IN_HW * IN_HW)       // 66049 floats per image
#define STRIP_F (9 * IN_HW)           // 2313 floats per 9-row strip
#define BUF_F   2324                  // strip + shift(<=3) + round-up slack

__device__ __forceinline__ void bulk_copy(uint32_t dst, const void* src,
                                          uint32_t bytes, uint32_t mbar)
{
    asm volatile(
        "cp.async.bulk.shared::cta.global.mbarrier::complete_tx::bytes "
        "[%0], [%1], %2, [%3];"
        :: "r"(dst), "l"(src), "r"(bytes), "r"(mbar) : "memory");
}

__device__ __forceinline__ void mbar_init(uint32_t mbar, uint32_t count)
{
    asm volatile("mbarrier.init.shared.b64 [%0], %1;" :: "r"(mbar), "r"(count) : "memory");
}

__device__ __forceinline__ void mbar_expect_tx(uint32_t mbar, uint32_t bytes)
{
    asm volatile("mbarrier.arrive.expect_tx.shared.b64 _, [%0], %1;"
                 :: "r"(mbar), "r"(bytes) : "memory");
}

__device__ __forceinline__ void mbar_wait(uint32_t mbar, uint32_t parity)
{
    asm volatile(
        "{\n\t"
        ".reg .pred P;\n\t"
        "WAIT_%=:\n\t"
        "mbarrier.try_wait.parity.acquire.cta.shared::cta.b64 P, [%0], %1, 0x989680;\n\t"
        "@P bra.uni DONE_%=;\n\t"
        "bra.uni WAIT_%=;\n\t"
        "DONE_%=:\n\t"
        "}"
        :: "r"(mbar), "r"(parity) : "memory");
}

__global__ __launch_bounds__(256, 8)
void conv_enhanced_kernel(const float* __restrict__ x,
                          const float* __restrict__ w,
                          const float* __restrict__ bias,
                          float* __restrict__ out)
{
    __shared__ alignas(16) float buf[2][BUF_F];
    __shared__ alignas(8) unsigned long long mbar_s[2];

    const int img = blockIdx.x >> 4;          // 64 images
    const int ss  = blockIdx.x & 15;          // super-strip: tiles 2ss, 2ss+1
    const int tid = threadIdx.x;

    uint32_t smem_base;
    asm("{ .reg .u64 t; cvta.to.shared.u64 t, %1; cvt.u32.u64 %0, t; }"
        : "=r"(smem_base) : "l"((const void*)&buf[0][0]));
    uint32_t mb0;
    asm("{ .reg .u64 t; cvta.to.shared.u64 t, %1; cvt.u32.u64 %0, t; }"
        : "=r"(mb0) : "l"((const void*)&mbar_s[0]));

    // per-tile source geometry (tile t covers input rows 8t..8t+8)
    int   row0[2];
    const float* srcA[2];     // 16B-aligned-down source
    uint32_t copy_sz[2];
    int   shift_f[2];

#pragma unroll
    for (int ti = 0; ti < 2; ++ti) {
        row0[ti] = (2 * ss + ti) * 8;
        const long long eoff = (long long)img * IMG_E + (long long)row0[ti] * IN_HW;
        const int ef = (int)(eoff & 3);               // float misalignment 0..3
        srcA[ti]    = x + (eoff - ef);                // 16B aligned
        shift_f[ti] = ef;
        copy_sz[ti] = (uint32_t)(((ef + STRIP_F) * 4 + 15) & ~15);
    }

    if (tid == 0) {
        mbar_init(mb0,     1);
        mbar_init(mb0 + 8, 1);
    }
    __syncthreads();

    if (tid == 0) {
#pragma unroll
        for (int ti = 0; ti < 2; ++ti) {
            const uint32_t mb = mb0 + 8 * ti;
            mbar_expect_tx(mb, copy_sz[ti]);
            bulk_copy(smem_base + ti * (BUF_F * 4), srcA[ti], copy_sz[ti], mb);
        }
    }

    const float w00 = __ldg(w + 0);
    const float w01 = __ldg(w + 1);
    const float w10 = __ldg(w + 2);
    const float w11 = __ldg(w + 3);
    const float bb  = __ldg(bias);

    const int pr = tid >> 6;                  // 0..3 patch-row within tile
    const int pp = tid & 63;                  // patch-pair
    const int c  = pp * 4;

    float* ob  = out + (size_t)img * (2 * OUT_HW * OUT_HW);
    float* ob1 = ob + OUT_HW * OUT_HW;

#pragma unroll 1
    for (int ti = 0; ti < 2; ++ti) {
        mbar_wait(mb0 + 8 * ti, 0);

        const float* t = buf[ti] + shift_f[ti] + (2 * pr) * IN_HW + c;

        float x0[5], x1[5], x2[5];
#pragma unroll
        for (int j = 0; j < 5; ++j) x0[j] = t[j];
#pragma unroll
        for (int j = 0; j < 5; ++j) x1[j] = t[IN_HW + j];
#pragma unroll
        for (int j = 0; j < 5; ++j) x2[j] = t[2 * IN_HW + j];

        float p0[4], p1[4];
#pragma unroll
        for (int j = 0; j < 4; ++j) {
            p0[j] = fmaxf(fmaf(w00, x0[j], fmaf(w01, x0[j+1],
                            fmaf(w10, x1[j], fmaf(w11, x1[j+1], bb)))), 0.f);
            p1[j] = fmaxf(fmaf(w00, x1[j], fmaf(w01, x1[j+1],
                            fmaf(w10, x2[j], fmaf(w11, x2[j+1], bb)))), 0.f);
        }

        const float qA = __cosf(p0[0]) * __cosf(p0[1]) * __cosf(p1[1]);
        const float qB = __cosf(p0[2]) * __cosf(p0[3]) * __cosf(p1[3]);

        const int orow = row0[ti] + 2 * pr;
        const int o0   = orow * OUT_HW + c;   // 16B aligned

        *reinterpret_cast<float4*>(ob + o0)          = make_float4(p0[0], p0[1], p0[2], p0[3]);
        *reinterpret_cast<float4*>(ob + o0 + OUT_HW) = make_float4(p1[0], p1[1], p1[2], p1[3]);
        const float4 qv = make_float4(qA, qA, qB, qB);
        *reinterpret_cast<float4*>(ob1 + o0)          = qv;
        *reinterpret_cast<float4*>(ob1 + o0 + OUT_HW) = qv;
    }
}

extern "C" void kernel_launch(void* const* d_in, const int* in_sizes, int n_in,
                              void* d_out, int out_size)
{
    const float* x      = (const float*)d_in[0];
    const float* conv_w = (const float*)d_in[1];
    const float* conv_b = (const float*)d_in[2];
    // d_in[3] = qparams: provably unused
    float* out = (float*)d_out;

    conv_enhanced_kernel<<<64 * 16, 256>>>(x, conv_w, conv_b, out);
}